// round 7
// baseline (speedup 1.0000x reference)
#include <cuda_runtime.h>
#include <math.h>

#define DIM   1024
#define VOCAB 50257
#define G     148
#define NROW  7        // rows per block: 148*7 = 1036 >= 1024

__device__ float g_z[DIM];
__device__ unsigned int g_bar;      // zero-init; reset by finishing block
__device__ unsigned int g_maxkey;   // order-preserving float key; reset too

// Order-preserving float <-> uint key (works for any sign).
__device__ __forceinline__ unsigned int fkey(float f) {
    unsigned int b = __float_as_uint(f);
    return ((int)b < 0) ? ~b : (b | 0x80000000u);
}
__device__ __forceinline__ float funkey(unsigned int k) {
    unsigned int b = (k & 0x80000000u) ? (k & 0x7FFFFFFFu) : ~k;
    return __uint_as_float(b);
}

__global__ void __launch_bounds__(256, 1)
fused_kernel(const float* __restrict__ filters,
             const float* __restrict__ w_t,
             const float* __restrict__ w_h,
             float* __restrict__ out)
{
    const int tid  = threadIdx.x;
    const int bid  = blockIdx.x;
    const int warp = tid >> 5, lane = tid & 31;

    __shared__ float s_y[DIM];
    __shared__ float s_zb[NROW];
    __shared__ float sred[8];
    __shared__ float s_bcast[2];
    __shared__ int   s_last;

    // ---- Gather: 4 strided loads per thread (issued first; gates the sync) ----
    float gv0 = filters[(size_t)(tid        ) * VOCAB];
    float gv1 = filters[(size_t)(tid +  256) * VOCAB];
    float gv2 = filters[(size_t)(tid +  512) * VOCAB];
    float gv3 = filters[(size_t)(tid +  768) * VOCAB];

    // ---- Dual-row weight loads: warp w owns row bid*7+w for BOTH matrices ----
    const int  row    = bid * NROW + warp;
    const bool active = (warp < NROW) && (row < DIM);
    float4 wvt[8], wvh[8];
    if (active) {
        const float4* At = (const float4*)(w_t + (size_t)row * DIM);
        const float4* Ah = (const float4*)(w_h + (size_t)row * DIM);
        #pragma unroll
        for (int k = 0; k < 8; k++) { wvt[k] = At[k * 32 + lane]; wvh[k] = Ah[k * 32 + lane]; }
    }

    // Stage y (relu; element DIM-1 passes through -- it's tid+768 == 1023).
    s_y[tid      ] = fmaxf(gv0, 0.0f);
    s_y[tid + 256] = fmaxf(gv1, 0.0f);
    s_y[tid + 512] = fmaxf(gv2, 0.0f);
    s_y[tid + 768] = (tid + 768 == DIM - 1) ? gv3 : fmaxf(gv3, 0.0f);
    __syncthreads();

    if (active) {
        const float4* y4 = (const float4*)s_y;
        float t0 = 0.f, t1 = 0.f, h0 = 0.f, h1 = 0.f;
        #pragma unroll
        for (int k = 0; k < 8; k += 2) {
            float4 ya = y4[k * 32 + lane];
            float4 yb = y4[(k + 1) * 32 + lane];
            t0 += wvt[k].x*ya.x + wvt[k].y*ya.y + wvt[k].z*ya.z + wvt[k].w*ya.w;
            t1 += wvt[k+1].x*yb.x + wvt[k+1].y*yb.y + wvt[k+1].z*yb.z + wvt[k+1].w*yb.w;
            h0 += wvh[k].x*ya.x + wvh[k].y*ya.y + wvh[k].z*ya.z + wvh[k].w*ya.w;
            h1 += wvh[k+1].x*yb.x + wvh[k+1].y*yb.y + wvh[k+1].z*yb.z + wvh[k+1].w*yb.w;
        }
        float at = t0 + t1, ah = h0 + h1;
        #pragma unroll
        for (int o = 16; o; o >>= 1) {
            at += __shfl_xor_sync(0xffffffffu, at, o);
            ah += __shfl_xor_sync(0xffffffffu, ah, o);
        }
        if (lane == 0) {
            float t = __fdividef(1.0f, 1.0f + __expf(-at));
            float g = fmaxf(ah, 0.0f);
            float z = t * g + (1.0f - t) * s_y[row];
            __stcg(&g_z[row], z);
            s_zb[warp] = z;
        }
    } else if (warp < NROW && lane == 0) {
        s_zb[warp] = -1e30f;   // inactive rows don't affect the block max
    }
    __syncthreads();

    // One atomicMax + release + arrive per block (thread 0 only).
    if (tid == 0) {
        float m = s_zb[0];
        #pragma unroll
        for (int k = 1; k < NROW; k++) m = fmaxf(m, s_zb[k]);
        atomicMax(&g_maxkey, fkey(m));
        __threadfence();                       // release z stores + maxkey
        unsigned int old = atomicAdd(&g_bar, 1u);
        s_last = (old == G - 1u);
    }
    __syncthreads();
    if (!s_last) return;

    // -------- Finishing block: M is final, all z visible --------
    __threadfence();                           // acquire
    if (tid == 0) s_bcast[0] = funkey(__ldcg(&g_maxkey));
    __syncthreads();
    const float M = s_bcast[0];

    float z0 = __ldcg(&g_z[tid      ]);
    float z1 = __ldcg(&g_z[tid + 256]);
    float z2 = __ldcg(&g_z[tid + 512]);
    float z3 = __ldcg(&g_z[tid + 768]);
    float s  = __expf(z0 - M) + __expf(z1 - M) + __expf(z2 - M) + __expf(z3 - M);

    #pragma unroll
    for (int o = 16; o; o >>= 1) s += __shfl_xor_sync(0xffffffffu, s, o);
    if (lane == 0) sred[warp] = s;
    __syncthreads();
    if (warp == 0) {
        float v = (lane < 8) ? sred[lane] : 0.0f;
        #pragma unroll
        for (int o = 4; o; o >>= 1) v += __shfl_xor_sync(0xffffffffu, v, o);
        if (lane == 0) s_bcast[1] = M + __logf(v);
    }
    __syncthreads();
    const float lse = s_bcast[1];

    out[tid      ] = z0 - lse;
    out[tid + 256] = z1 - lse;
    out[tid + 512] = z2 - lse;
    out[tid + 768] = z3 - lse;

    __syncthreads();
    if (tid == 0) { g_bar = 0u; g_maxkey = 0u; }   // reset for next replay
}

extern "C" void kernel_launch(void* const* d_in, const int* in_sizes, int n_in,
                              void* d_out, int out_size) {
    // metadata order: input (int32, unused), filters, w_t, w_h
    const float* filters = (const float*)d_in[1];
    const float* w_t     = (const float*)d_in[2];
    const float* w_h     = (const float*)d_in[3];
    float* out           = (float*)d_out;

    fused_kernel<<<G, 256>>>(filters, w_t, w_h, out);
}